// round 1
// baseline (speedup 1.0000x reference)
#include <cuda_runtime.h>
#include <math.h>

// TopKRouter: logits = x @ W_gate^T, softmax, top-2, renormalized weights.
// N = 16384 tokens, D = 2048, E = 64 experts.
// Output layout (float32, out_size = N*68):
//   [0,        2N)  : top_k_weights  (N,2)
//   [2N,       4N)  : top_k_indices  (N,2) cast to float
//   [4N, 4N + 64N)  : router_logits  (N,64)

#define DMODEL 2048
#define NEXP   64
#define BM     64            // tokens per block
#define BK     16            // k-slice per iteration
#define KIT    (DMODEL/BK)   // 128 iterations
#define NTHREADS 256

// packed fp32x2 FMA (Blackwell PTX-only FFMA2): d = a*b + d elementwise on 2 floats
#define FMA2(d, a, b) asm("fma.rn.f32x2 %0, %1, %2, %3;" : "=l"(d) : "l"(a), "l"(b), "l"(d))

__device__ __forceinline__ float f2lo(unsigned long long v) {
    return __uint_as_float((unsigned int)(v & 0xffffffffull));
}
__device__ __forceinline__ float f2hi(unsigned long long v) {
    return __uint_as_float((unsigned int)(v >> 32));
}

// Shared memory:
//   xs (dup pairs): [2][BK][2*BM] floats = 2*16*128*4 = 16384 B
//   ws            : [2][BK][NEXP] floats = 2*16*64*4  =  8192 B
//   epilogue L    : [BM][68] floats = 17408 B  (unioned over the above)
#define SMEM_BYTES 24576
#define XS_OFF 0
#define WS_OFF 16384
#define LPAD 68

__global__ __launch_bounds__(NTHREADS, 2)
void router_kernel(const float* __restrict__ x, const float* __restrict__ Wg,
                   float* __restrict__ w_out, float* __restrict__ i_out,
                   float* __restrict__ l_out)
{
    __shared__ __align__(16) unsigned char smem[SMEM_BYTES];
    float* xs = (float*)(smem + XS_OFF);   // [2][BK][128] (each token value duplicated)
    float* ws = (float*)(smem + WS_OFF);   // [2][BK][64]

    const int tid = threadIdx.x;
    const int tx  = tid & 15;      // expert group: experts tx*4 .. tx*4+3
    const int ty  = tid >> 4;      // token group:  tokens  ty*4 .. ty*4+3
    const int tx4 = tx * 4;
    const int ty4 = ty * 4;
    const int t0  = blockIdx.x * BM;

    // loader mapping: each thread loads one float4 of x and one float4 of W per tile
    const int lrow = tid >> 2;        // 0..63 : token row (x) / expert row (W)
    const int kc   = (tid & 3) * 4;   // k offset within BK

    const float* xg = x  + (size_t)(t0 + lrow) * DMODEL + kc;
    const float* wg = Wg + (size_t)lrow * DMODEL + kc;

    // acc[t][p]: t = local token 0..3 (row ty4+t), p = expert pair 0..1
    // lo half = expert tx4+2p, hi half = expert tx4+2p+1
    unsigned long long acc[4][2];
    #pragma unroll
    for (int t = 0; t < 4; t++) { acc[t][0] = 0ull; acc[t][1] = 0ull; }

    // prologue: tile 0
    float4 xr = *(const float4*)xg;
    float4 wr = *(const float4*)wg;
    {
        float* xb = xs;  // buf 0
        float* wb = ws;
        xb[(kc+0)*128 + 2*lrow] = xr.x; xb[(kc+0)*128 + 2*lrow + 1] = xr.x;
        xb[(kc+1)*128 + 2*lrow] = xr.y; xb[(kc+1)*128 + 2*lrow + 1] = xr.y;
        xb[(kc+2)*128 + 2*lrow] = xr.z; xb[(kc+2)*128 + 2*lrow + 1] = xr.z;
        xb[(kc+3)*128 + 2*lrow] = xr.w; xb[(kc+3)*128 + 2*lrow + 1] = xr.w;
        wb[(kc+0)*NEXP + lrow] = wr.x;
        wb[(kc+1)*NEXP + lrow] = wr.y;
        wb[(kc+2)*NEXP + lrow] = wr.z;
        wb[(kc+3)*NEXP + lrow] = wr.w;
    }
    __syncthreads();

    for (int it = 0; it < KIT; ++it) {
        const int cur = it & 1;
        // prefetch next tile into registers (latency overlapped with compute)
        if (it + 1 < KIT) {
            xr = *(const float4*)(xg + (it + 1) * BK);
            wr = *(const float4*)(wg + (it + 1) * BK);
        }

        const float* xb = xs + cur * BK * 128;
        const float* wb = ws + cur * BK * NEXP;

        #pragma unroll
        for (int kk = 0; kk < BK; kk++) {
            // duplicated token pairs: x01.x = dup(x[ty4+0]), x01.y = dup(x[ty4+1]) ...
            ulonglong2 x01 = *(const ulonglong2*)(xb + kk * 128 + 2 * ty4);
            ulonglong2 x23 = *(const ulonglong2*)(xb + kk * 128 + 2 * ty4 + 4);
            // natural expert pairs: wp.x = (w[e0], w[e0+1]), wp.y = (w[e0+2], w[e0+3])
            ulonglong2 wp  = *(const ulonglong2*)(wb + kk * NEXP + tx4);

            FMA2(acc[0][0], x01.x, wp.x); FMA2(acc[0][1], x01.x, wp.y);
            FMA2(acc[1][0], x01.y, wp.x); FMA2(acc[1][1], x01.y, wp.y);
            FMA2(acc[2][0], x23.x, wp.x); FMA2(acc[2][1], x23.x, wp.y);
            FMA2(acc[3][0], x23.y, wp.x); FMA2(acc[3][1], x23.y, wp.y);
        }

        if (it + 1 < KIT) {
            float* xb2 = xs + (cur ^ 1) * BK * 128;
            float* wb2 = ws + (cur ^ 1) * BK * NEXP;
            xb2[(kc+0)*128 + 2*lrow] = xr.x; xb2[(kc+0)*128 + 2*lrow + 1] = xr.x;
            xb2[(kc+1)*128 + 2*lrow] = xr.y; xb2[(kc+1)*128 + 2*lrow + 1] = xr.y;
            xb2[(kc+2)*128 + 2*lrow] = xr.z; xb2[(kc+2)*128 + 2*lrow + 1] = xr.z;
            xb2[(kc+3)*128 + 2*lrow] = xr.w; xb2[(kc+3)*128 + 2*lrow + 1] = xr.w;
            wb2[(kc+0)*NEXP + lrow] = wr.x;
            wb2[(kc+1)*NEXP + lrow] = wr.y;
            wb2[(kc+2)*NEXP + lrow] = wr.z;
            wb2[(kc+3)*NEXP + lrow] = wr.w;
        }
        __syncthreads();
    }

    // ---- epilogue: write logits (global + smem), then per-token softmax/top-2 ----
    float* L = (float*)smem;  // [BM][LPAD], reuses GEMM buffers (safe: loop ended with sync)

    #pragma unroll
    for (int t = 0; t < 4; t++) {
        const int tok = ty4 + t;
        float4 v;
        v.x = f2lo(acc[t][0]); v.y = f2hi(acc[t][0]);
        v.z = f2lo(acc[t][1]); v.w = f2hi(acc[t][1]);
        *(float4*)(l_out + (size_t)(t0 + tok) * NEXP + tx4) = v;
        *(float4*)(L + tok * LPAD + tx4) = v;   // 272B row stride: 16B aligned
    }
    __syncthreads();

    if (tid < BM) {
        const float* row = L + tid * LPAD;
        float v1 = -INFINITY, v2 = -INFINITY;
        int   i1 = 0, i2 = 0;
        #pragma unroll 8
        for (int e = 0; e < NEXP; e++) {
            float v = row[e];
            if (v > v1) { v2 = v1; i2 = i1; v1 = v; i1 = e; }
            else if (v > v2) { v2 = v; i2 = e; }
        }
        float S = 0.0f;
        #pragma unroll 8
        for (int e = 0; e < NEXP; e++) S += expf(row[e] - v1);
        const float p1 = 1.0f / S;              // expf(v1 - v1)/S
        const float p2 = expf(v2 - v1) / S;
        const float inv = 1.0f / (p1 + p2 + 1e-10f);
        const size_t n = (size_t)(t0 + tid);
        w_out[2 * n]     = p1 * inv;
        w_out[2 * n + 1] = p2 * inv;
        i_out[2 * n]     = (float)i1;
        i_out[2 * n + 1] = (float)i2;
    }
}

extern "C" void kernel_launch(void* const* d_in, const int* in_sizes, int n_in,
                              void* d_out, int out_size)
{
    const float* x  = (const float*)d_in[0];
    const float* Wg = (const float*)d_in[1];
    const int N = in_sizes[0] / DMODEL;       // 16384

    float* out   = (float*)d_out;
    float* w_out = out;
    float* i_out = out + (size_t)N * 2;
    float* l_out = out + (size_t)N * 4;

    router_kernel<<<N / BM, NTHREADS>>>(x, Wg, w_out, i_out, l_out);
}

// round 2
// speedup vs baseline: 1.1402x; 1.1402x over previous
#include <cuda_runtime.h>
#include <math.h>

// TopKRouter: logits = x @ W_gate^T (N=16384, D=2048, E=64), softmax, top-2.
// Two kernels:
//   1) gemm_split_kernel: K-split=4 partial GEMM into __device__ scratch.
//      64 threads/block, tile 8 tokens x 8 experts per thread (FFMA2 pairs).
//   2) reduce_topk_kernel: sum partials, write logits, fused softmax/top-2.
// Output layout (float32, out_size = N*68):
//   [0,2N): weights   [2N,4N): indices (float)   [4N,68N): logits

#define DMODEL  2048
#define NEXP    64
#define NTOKMAX 16384
#define BM      64
#define BK      16
#define NSPLIT  4
#define KCHUNK  (DMODEL / NSPLIT)   // 512
#define NTILES  (KCHUNK / BK)       // 32

__device__ float g_scratch[(size_t)NSPLIT * NTOKMAX * NEXP];  // 16 MB static

// packed fp32x2 FMA: d = a*b + d (elementwise on 2 floats)
#define FMA2(d, a, b) asm("fma.rn.f32x2 %0, %1, %2, %3;" : "=l"(d) : "l"(a), "l"(b), "l"(d))

__device__ __forceinline__ float f2lo(unsigned long long v) {
    return __uint_as_float((unsigned int)(v & 0xffffffffull));
}
__device__ __forceinline__ float f2hi(unsigned long long v) {
    return __uint_as_float((unsigned int)(v >> 32));
}

__global__ __launch_bounds__(64, 7)
void gemm_split_kernel(const float* __restrict__ x, const float* __restrict__ Wg,
                       float* __restrict__ scratch, int ntok)
{
    // xs: token values duplicated in pairs -> FFMA2 x-operand loads are LDS.128
    __shared__ __align__(16) float xs[2][BK][2 * BM];   // 16 KB
    __shared__ __align__(16) float ws[2][BK][NEXP];     //  8 KB

    const int tid = threadIdx.x;
    const int tx  = tid & 7;        // expert col: experts tx*8 .. tx*8+7
    const int ty  = tid >> 3;       // token row:  tokens  ty*8 .. ty*8+7

    const int nblk_t = ntok / BM;                 // 256
    const int tb = blockIdx.x % nblk_t;
    const int sp = blockIdx.x / nblk_t;           // k-split id 0..3
    const int t0 = tb * BM;
    const int k0 = sp * KCHUNK;

    // loader: 16 rows per pass x 4 passes; thread handles 4 k-floats of a row
    const int lr = tid >> 2;        // 0..15 row-within-pass
    const int kq = (tid & 3) * 4;   // k offset 0,4,8,12

    const float* xg = x  + (size_t)(t0 + lr) * DMODEL + k0 + kq;
    const float* wg = Wg + (size_t)lr * DMODEL + k0 + kq;

    // acc[t][ep]: t = local token 0..7, ep = expert pair 0..3
    // lo half = expert tx*8+2ep, hi half = +1
    unsigned long long acc[8][4];
    #pragma unroll
    for (int t = 0; t < 8; t++)
        #pragma unroll
        for (int e = 0; e < 4; e++) acc[t][e] = 0ull;

    float4 xr[4], wr[4];

    // prologue: stage tile 0
    #pragma unroll
    for (int p = 0; p < 4; p++) {
        xr[p] = *(const float4*)(xg + (size_t)p * 16 * DMODEL);
        wr[p] = *(const float4*)(wg + (size_t)p * 16 * DMODEL);
    }
    #pragma unroll
    for (int p = 0; p < 4; p++) {
        const int row = p * 16 + lr;
        xs[0][kq + 0][2*row] = xr[p].x; xs[0][kq + 0][2*row + 1] = xr[p].x;
        xs[0][kq + 1][2*row] = xr[p].y; xs[0][kq + 1][2*row + 1] = xr[p].y;
        xs[0][kq + 2][2*row] = xr[p].z; xs[0][kq + 2][2*row + 1] = xr[p].z;
        xs[0][kq + 3][2*row] = xr[p].w; xs[0][kq + 3][2*row + 1] = xr[p].w;
        ws[0][kq + 0][row] = wr[p].x;
        ws[0][kq + 1][row] = wr[p].y;
        ws[0][kq + 2][row] = wr[p].z;
        ws[0][kq + 3][row] = wr[p].w;
    }
    __syncthreads();

    for (int it = 0; it < NTILES; ++it) {
        const int cur = it & 1;

        // front-batched prefetch of next tile (8 x LDG.128 in flight)
        if (it + 1 < NTILES) {
            #pragma unroll
            for (int p = 0; p < 4; p++) {
                xr[p] = *(const float4*)(xg + (it + 1) * BK + (size_t)p * 16 * DMODEL);
                wr[p] = *(const float4*)(wg + (it + 1) * BK + (size_t)p * 16 * DMODEL);
            }
        }

        #pragma unroll
        for (int kk = 0; kk < BK; kk++) {
            const float* xrow = &xs[cur][kk][2 * (ty * 8)];
            const float* wrow = &ws[cur][kk][tx * 8];
            // natural expert pairs
            ulonglong2 w01 = *(const ulonglong2*)(wrow);       // (e0,e1),(e2,e3)
            ulonglong2 w23 = *(const ulonglong2*)(wrow + 4);   // (e4,e5),(e6,e7)
            #pragma unroll
            for (int tp = 0; tp < 4; tp++) {
                // duplicated token pairs: xp.x = dup(tok 2tp), xp.y = dup(tok 2tp+1)
                ulonglong2 xp = *(const ulonglong2*)(xrow + 4 * tp);
                FMA2(acc[2*tp  ][0], xp.x, w01.x);
                FMA2(acc[2*tp  ][1], xp.x, w01.y);
                FMA2(acc[2*tp  ][2], xp.x, w23.x);
                FMA2(acc[2*tp  ][3], xp.x, w23.y);
                FMA2(acc[2*tp+1][0], xp.y, w01.x);
                FMA2(acc[2*tp+1][1], xp.y, w01.y);
                FMA2(acc[2*tp+1][2], xp.y, w23.x);
                FMA2(acc[2*tp+1][3], xp.y, w23.y);
            }
        }

        if (it + 1 < NTILES) {
            const int nb = cur ^ 1;
            #pragma unroll
            for (int p = 0; p < 4; p++) {
                const int row = p * 16 + lr;
                xs[nb][kq + 0][2*row] = xr[p].x; xs[nb][kq + 0][2*row + 1] = xr[p].x;
                xs[nb][kq + 1][2*row] = xr[p].y; xs[nb][kq + 1][2*row + 1] = xr[p].y;
                xs[nb][kq + 2][2*row] = xr[p].z; xs[nb][kq + 2][2*row + 1] = xr[p].z;
                xs[nb][kq + 3][2*row] = xr[p].w; xs[nb][kq + 3][2*row + 1] = xr[p].w;
                ws[nb][kq + 0][row] = wr[p].x;
                ws[nb][kq + 1][row] = wr[p].y;
                ws[nb][kq + 2][row] = wr[p].z;
                ws[nb][kq + 3][row] = wr[p].w;
            }
        }
        __syncthreads();
    }

    // write partial logits: scratch[sp][token][expert]
    float* dst = scratch + ((size_t)sp * ntok + t0 + ty * 8) * NEXP + tx * 8;
    #pragma unroll
    for (int t = 0; t < 8; t++) {
        float4 a, b;
        a.x = f2lo(acc[t][0]); a.y = f2hi(acc[t][0]);
        a.z = f2lo(acc[t][1]); a.w = f2hi(acc[t][1]);
        b.x = f2lo(acc[t][2]); b.y = f2hi(acc[t][2]);
        b.z = f2lo(acc[t][3]); b.w = f2hi(acc[t][3]);
        *(float4*)(dst + (size_t)t * NEXP)     = a;
        *(float4*)(dst + (size_t)t * NEXP + 4) = b;
    }
}

__global__ __launch_bounds__(128)
void reduce_topk_kernel(const float* __restrict__ scratch,
                        float* __restrict__ w_out, float* __restrict__ i_out,
                        float* __restrict__ l_out, int ntok)
{
    const int n = blockIdx.x * 128 + threadIdx.x;
    if (n >= ntok) return;

    float L[NEXP];
    {
        const float* s = scratch + (size_t)n * NEXP;
        #pragma unroll
        for (int j = 0; j < 16; j++) {
            float4 v = *(const float4*)(s + j * 4);
            L[4*j] = v.x; L[4*j+1] = v.y; L[4*j+2] = v.z; L[4*j+3] = v.w;
        }
    }
    #pragma unroll
    for (int sp = 1; sp < NSPLIT; sp++) {
        const float* s = scratch + ((size_t)sp * ntok + n) * NEXP;
        #pragma unroll
        for (int j = 0; j < 16; j++) {
            float4 v = *(const float4*)(s + j * 4);
            L[4*j] += v.x; L[4*j+1] += v.y; L[4*j+2] += v.z; L[4*j+3] += v.w;
        }
    }

    // logits out
    #pragma unroll
    for (int j = 0; j < 16; j++) {
        float4 v;
        v.x = L[4*j]; v.y = L[4*j+1]; v.z = L[4*j+2]; v.w = L[4*j+3];
        *(float4*)(l_out + (size_t)n * NEXP + j * 4) = v;
    }

    // top-2 + softmax (exact reference formula)
    float v1 = -INFINITY, v2 = -INFINITY;
    int   i1 = 0, i2 = 0;
    #pragma unroll
    for (int e = 0; e < NEXP; e++) {
        float v = L[e];
        if (v > v1)      { v2 = v1; i2 = i1; v1 = v; i1 = e; }
        else if (v > v2) { v2 = v;  i2 = e; }
    }
    float S = 0.0f;
    #pragma unroll
    for (int e = 0; e < NEXP; e++) S += __expf(L[e] - v1);
    const float p1  = 1.0f / S;
    const float p2  = __expf(v2 - v1) / S;
    const float inv = 1.0f / (p1 + p2 + 1e-10f);
    w_out[2*n]     = p1 * inv;
    w_out[2*n + 1] = p2 * inv;
    i_out[2*n]     = (float)i1;
    i_out[2*n + 1] = (float)i2;
}

extern "C" void kernel_launch(void* const* d_in, const int* in_sizes, int n_in,
                              void* d_out, int out_size)
{
    const float* x  = (const float*)d_in[0];
    const float* Wg = (const float*)d_in[1];
    const int N = in_sizes[0] / DMODEL;       // 16384

    float* out   = (float*)d_out;
    float* w_out = out;
    float* i_out = out + (size_t)N * 2;
    float* l_out = out + (size_t)N * 4;

    float* scratch = nullptr;
    cudaGetSymbolAddress((void**)&scratch, g_scratch);

    gemm_split_kernel<<<(N / BM) * NSPLIT, 64>>>(x, Wg, scratch, N);
    reduce_topk_kernel<<<(N + 127) / 128, 128>>>(scratch, w_out, i_out, l_out, N);
}

// round 6
// speedup vs baseline: 1.5848x; 1.3900x over previous
#include <cuda_runtime.h>
#include <math.h>
#include <stdint.h>

// TopKRouter: mma.sync 3-pass TF32 split GEMM (logits) + fp64 rescue for
// near-tied top-2 decisions (indices must match an fp32 reference exactly).
// logits = x @ W^T ~= xh@wh + xh@wl + xl@wh   (abs err ~1e-6, fine for output)
// Decision path: tokens whose top-2 margins < THR are re-ranked from exact
// fp64 dot products of the top-4 candidate experts (warp-cooperative).
// N=16384 tokens, D=2048, E=64.
// Output layout (float32): [0,2N) weights | [2N,4N) indices | [4N,68N) logits

#define DMODEL   2048
#define NEXP     64
#define BM       128
#define KC       32
#define NCHUNK   (DMODEL / KC)      // 64
#define NTHREADS 128
#define XPITCH   36                 // conflict-free smem pitch
#define LPITCH   65
#define THR      5e-4f              // near-tie rescue threshold

#define XH_OFF 0
#define XL_OFF (BM * XPITCH)
#define WH_OFF (2 * BM * XPITCH)
#define WL_OFF (2 * BM * XPITCH + NEXP * XPITCH)
#define SMEM_FLOATS (2 * BM * XPITCH + 2 * NEXP * XPITCH)
#define SMEM_BYTES  (SMEM_FLOATS * 4)   // 55296

#define MMA(c, a, b) asm volatile(                                        \
    "mma.sync.aligned.m16n8k8.row.col.f32.tf32.tf32.f32 "                 \
    "{%0,%1,%2,%3}, {%4,%5,%6,%7}, {%8,%9}, {%0,%1,%2,%3};"               \
    : "+f"((c)[0]), "+f"((c)[1]), "+f"((c)[2]), "+f"((c)[3])              \
    : "r"((a)[0]), "r"((a)[1]), "r"((a)[2]), "r"((a)[3]),                 \
      "r"((b)[0]), "r"((b)[1]))

static __device__ __forceinline__ uint32_t tf32_bits(float a) {
    uint32_t r;
    asm("cvt.rna.tf32.f32 %0, %1;" : "=r"(r) : "f"(a));
    return r;
}

__global__ __launch_bounds__(NTHREADS, 1)
void router_mma_kernel(const float* __restrict__ x, const float* __restrict__ Wg,
                       float* __restrict__ w_out, float* __restrict__ i_out,
                       float* __restrict__ l_out)
{
    extern __shared__ float sm[];
    uint32_t* smu = (uint32_t*)sm;

    const int tid = threadIdx.x;
    const int wid = tid >> 5;
    const int lid = tid & 31;
    const int g   = lid >> 2;
    const int t   = lid & 3;
    const int wm  = wid >> 1;
    const int wn  = wid & 1;
    const int t0  = blockIdx.x * BM;

    float c[4][4][4];
    #pragma unroll
    for (int i = 0; i < 4; i++)
        #pragma unroll
        for (int j = 0; j < 4; j++)
            #pragma unroll
            for (int k = 0; k < 4; k++) c[i][j][k] = 0.0f;

    const float4* xg = (const float4*)(x + (size_t)t0 * DMODEL);
    const float4* wg = (const float4*)Wg;

    float4 xr[8], wr[4];

    #pragma unroll
    for (int p = 0; p < 8; p++) {
        int id = tid + 128 * p;
        xr[p] = xg[(size_t)(id >> 3) * (DMODEL / 4) + (id & 7)];
    }
    #pragma unroll
    for (int p = 0; p < 4; p++) {
        int id = tid + 128 * p;
        wr[p] = wg[(size_t)(id >> 3) * (DMODEL / 4) + (id & 7)];
    }

    for (int ck = 0; ck < NCHUNK; ck++) {
        #pragma unroll
        for (int p = 0; p < 8; p++) {
            int id = tid + 128 * p;
            int r = id >> 3, q = id & 7;
            float4 v = xr[p], h, l;
            h.x = __uint_as_float(tf32_bits(v.x)); l.x = __uint_as_float(tf32_bits(v.x - h.x));
            h.y = __uint_as_float(tf32_bits(v.y)); l.y = __uint_as_float(tf32_bits(v.y - h.y));
            h.z = __uint_as_float(tf32_bits(v.z)); l.z = __uint_as_float(tf32_bits(v.z - h.z));
            h.w = __uint_as_float(tf32_bits(v.w)); l.w = __uint_as_float(tf32_bits(v.w - h.w));
            *(float4*)&sm[XH_OFF + r * XPITCH + q * 4] = h;
            *(float4*)&sm[XL_OFF + r * XPITCH + q * 4] = l;
        }
        #pragma unroll
        for (int p = 0; p < 4; p++) {
            int id = tid + 128 * p;
            int r = id >> 3, q = id & 7;
            float4 v = wr[p], h, l;
            h.x = __uint_as_float(tf32_bits(v.x)); l.x = __uint_as_float(tf32_bits(v.x - h.x));
            h.y = __uint_as_float(tf32_bits(v.y)); l.y = __uint_as_float(tf32_bits(v.y - h.y));
            h.z = __uint_as_float(tf32_bits(v.z)); l.z = __uint_as_float(tf32_bits(v.z - h.z));
            h.w = __uint_as_float(tf32_bits(v.w)); l.w = __uint_as_float(tf32_bits(v.w - h.w));
            *(float4*)&sm[WH_OFF + r * XPITCH + q * 4] = h;
            *(float4*)&sm[WL_OFF + r * XPITCH + q * 4] = l;
        }
        __syncthreads();

        if (ck + 1 < NCHUNK) {
            const int kq = (ck + 1) * (KC / 4);
            #pragma unroll
            for (int p = 0; p < 8; p++) {
                int id = tid + 128 * p;
                xr[p] = xg[(size_t)(id >> 3) * (DMODEL / 4) + kq + (id & 7)];
            }
            #pragma unroll
            for (int p = 0; p < 4; p++) {
                int id = tid + 128 * p;
                wr[p] = wg[(size_t)(id >> 3) * (DMODEL / 4) + kq + (id & 7)];
            }
        }

        #pragma unroll
        for (int s = 0; s < 4; s++) {
            uint32_t ah[4][4], al[4][4], bh[4][2], bl[4][2];
            const int cc = s * 8 + t;
            #pragma unroll
            for (int mt = 0; mt < 4; mt++) {
                const int r0 = wm * 64 + mt * 16 + g;
                ah[mt][0] = smu[XH_OFF + r0 * XPITCH + cc];
                ah[mt][1] = smu[XH_OFF + (r0 + 8) * XPITCH + cc];
                ah[mt][2] = smu[XH_OFF + r0 * XPITCH + cc + 4];
                ah[mt][3] = smu[XH_OFF + (r0 + 8) * XPITCH + cc + 4];
                al[mt][0] = smu[XL_OFF + r0 * XPITCH + cc];
                al[mt][1] = smu[XL_OFF + (r0 + 8) * XPITCH + cc];
                al[mt][2] = smu[XL_OFF + r0 * XPITCH + cc + 4];
                al[mt][3] = smu[XL_OFF + (r0 + 8) * XPITCH + cc + 4];
            }
            #pragma unroll
            for (int nt = 0; nt < 4; nt++) {
                const int e0 = wn * 32 + nt * 8 + g;
                bh[nt][0] = smu[WH_OFF + e0 * XPITCH + cc];
                bh[nt][1] = smu[WH_OFF + e0 * XPITCH + cc + 4];
                bl[nt][0] = smu[WL_OFF + e0 * XPITCH + cc];
                bl[nt][1] = smu[WL_OFF + e0 * XPITCH + cc + 4];
            }
            #pragma unroll
            for (int mt = 0; mt < 4; mt++)
                #pragma unroll
                for (int nt = 0; nt < 4; nt++) {
                    MMA(c[mt][nt], ah[mt], bh[nt]);
                    MMA(c[mt][nt], ah[mt], bl[nt]);
                    MMA(c[mt][nt], al[mt], bh[nt]);
                }
        }
        __syncthreads();
    }

    // ---- epilogue: accums -> smem logits [128][65] ----
    float* L = sm;
    #pragma unroll
    for (int mt = 0; mt < 4; mt++) {
        const int row = wm * 64 + mt * 16 + g;
        #pragma unroll
        for (int nt = 0; nt < 4; nt++) {
            const int col = wn * 32 + nt * 8 + 2 * t;
            L[row * LPITCH + col]           = c[mt][nt][0];
            L[row * LPITCH + col + 1]       = c[mt][nt][1];
            L[(row + 8) * LPITCH + col]     = c[mt][nt][2];
            L[(row + 8) * LPITCH + col + 1] = c[mt][nt][3];
        }
    }
    __syncthreads();

    // ---- per-token top-4 scan + near-tie fp64 rescue + softmax ----
    {
        const float* row = &L[tid * LPITCH];
        float v1 = -INFINITY, v2 = -INFINITY, v3 = -INFINITY, v4 = -INFINITY;
        int   i1 = 0, i2 = 0, i3 = 0, i4 = 0;
        #pragma unroll 8
        for (int e = 0; e < NEXP; e++) {
            float v = row[e];
            if (v > v1)      { v4=v3;i4=i3; v3=v2;i3=i2; v2=v1;i2=i1; v1=v;i1=e; }
            else if (v > v2) { v4=v3;i4=i3; v3=v2;i3=i2; v2=v;i2=e; }
            else if (v > v3) { v4=v3;i4=i3; v3=v;i3=e; }
            else if (v > v4) { v4=v;i4=e; }
        }

        const bool flagged = (v1 - v2 < THR) || (v2 - v3 < THR);
        unsigned m = __ballot_sync(0xffffffffu, flagged);
        while (m) {
            const int src = __ffs(m) - 1;
            m &= m - 1;
            const int tok = t0 + (tid & ~31) + src;
            int cand[4];
            cand[0] = __shfl_sync(0xffffffffu, i1, src);
            cand[1] = __shfl_sync(0xffffffffu, i2, src);
            cand[2] = __shfl_sync(0xffffffffu, i3, src);
            cand[3] = __shfl_sync(0xffffffffu, i4, src);

            const int slot = lid >> 3;        // expert slot 0..3
            const int kl   = lid & 7;         // k-lane 0..7
            const int e    = cand[slot];
            const float* xp = x  + (size_t)tok * DMODEL;
            const float* wp = Wg + (size_t)e   * DMODEL;

            double a0 = 0.0, a1 = 0.0, a2 = 0.0, a3 = 0.0;
            #pragma unroll 4
            for (int j = 0; j < 256; j += 4) {
                int k0 = (j + 0) * 8 + kl;
                int k1 = (j + 1) * 8 + kl;
                int k2 = (j + 2) * 8 + kl;
                int k3 = (j + 3) * 8 + kl;
                a0 = fma((double)xp[k0], (double)wp[k0], a0);
                a1 = fma((double)xp[k1], (double)wp[k1], a1);
                a2 = fma((double)xp[k2], (double)wp[k2], a2);
                a3 = fma((double)xp[k3], (double)wp[k3], a3);
            }
            double tot = (a0 + a1) + (a2 + a3);
            tot += __shfl_xor_sync(0xffffffffu, tot, 4);
            tot += __shfl_xor_sync(0xffffffffu, tot, 2);
            tot += __shfl_xor_sync(0xffffffffu, tot, 1);

            double gv[4];
            gv[0] = __shfl_sync(0xffffffffu, tot, 0);
            gv[1] = __shfl_sync(0xffffffffu, tot, 8);
            gv[2] = __shfl_sync(0xffffffffu, tot, 16);
            gv[3] = __shfl_sync(0xffffffffu, tot, 24);

            if (lid == src) {
                // rank 4 candidates; ties (exact) -> lower expert index first
                int o1 = 0;
                #pragma unroll
                for (int s = 1; s < 4; s++)
                    if (gv[s] > gv[o1] || (gv[s] == gv[o1] && cand[s] < cand[o1])) o1 = s;
                int o2 = (o1 == 0) ? 1 : 0;
                #pragma unroll
                for (int s = 0; s < 4; s++) {
                    if (s == o1 || s == o2) continue;
                    if (gv[s] > gv[o2] || (gv[s] == gv[o2] && cand[s] < cand[o2])) o2 = s;
                }
                i1 = cand[o1]; i2 = cand[o2];
                v1 = row[i1];  v2 = row[i2];
            }
        }

        float S = 0.0f;
        #pragma unroll 8
        for (int e = 0; e < NEXP; e++) S += expf(row[e] - v1);
        const float p1  = expf(row[i1] - v1) / S;   // = 1/S normally
        const float p2  = expf(v2 - v1) / S;
        const float inv = 1.0f / (p1 + p2 + 1e-10f);
        const size_t n = (size_t)(t0 + tid);
        w_out[2 * n]     = p1 * inv;
        w_out[2 * n + 1] = p2 * inv;
        i_out[2 * n]     = (float)i1;
        i_out[2 * n + 1] = (float)i2;
    }

    // coalesced logits store from smem
    #pragma unroll
    for (int p = 0; p < 16; p++) {
        int id = tid + 128 * p;
        int rr = id >> 4, q = id & 15;
        float4 v;
        v.x = L[rr * LPITCH + 4 * q];
        v.y = L[rr * LPITCH + 4 * q + 1];
        v.z = L[rr * LPITCH + 4 * q + 2];
        v.w = L[rr * LPITCH + 4 * q + 3];
        *(float4*)(l_out + (size_t)(t0 + rr) * NEXP + 4 * q) = v;
    }
}

extern "C" void kernel_launch(void* const* d_in, const int* in_sizes, int n_in,
                              void* d_out, int out_size)
{
    const float* x  = (const float*)d_in[0];
    const float* Wg = (const float*)d_in[1];
    const int N = in_sizes[0] / DMODEL;       // 16384

    float* out   = (float*)d_out;
    float* w_out = out;
    float* i_out = out + (size_t)N * 2;
    float* l_out = out + (size_t)N * 4;

    cudaFuncSetAttribute(router_mma_kernel,
                         cudaFuncAttributeMaxDynamicSharedMemorySize, SMEM_BYTES);
    router_mma_kernel<<<N / BM, NTHREADS, SMEM_BYTES>>>(x, Wg, w_out, i_out, l_out);
}

// round 7
// speedup vs baseline: 1.5912x; 1.0040x over previous
#include <cuda_runtime.h>
#include <math.h>
#include <stdint.h>

// TopKRouter: mma.sync 3-pass TF32 split GEMM + fp64 rescue for near-ties.
// R7: BM=64 (grid 256, fills 148 SMs, 2 CTAs/SM), warp tile 32x32,
//     double-buffered smem with one barrier per K-chunk.
// Output layout (float32): [0,2N) weights | [2N,4N) indices | [4N,68N) logits

#define DMODEL   2048
#define NEXP     64
#define BM       64
#define KC       32
#define NCHUNK   (DMODEL / KC)      // 64
#define NTHREADS 128
#define XPITCH   36                 // conflict-free smem pitch
#define LPITCH   65
#define THR      5e-4f              // near-tie rescue threshold

// per-buffer layout (floats): XH | XL | WH | WL, each 64*36 = 2304
#define TSZ   (BM * XPITCH)         // 2304
#define SBUF  (4 * TSZ)             // 9216 floats per buffer
#define SMEM_FLOATS (2 * SBUF)      // 18432
#define SMEM_BYTES  (SMEM_FLOATS * 4)   // 73728

#define MMA(c, a, b) asm volatile(                                        \
    "mma.sync.aligned.m16n8k8.row.col.f32.tf32.tf32.f32 "                 \
    "{%0,%1,%2,%3}, {%4,%5,%6,%7}, {%8,%9}, {%0,%1,%2,%3};"               \
    : "+f"((c)[0]), "+f"((c)[1]), "+f"((c)[2]), "+f"((c)[3])              \
    : "r"((a)[0]), "r"((a)[1]), "r"((a)[2]), "r"((a)[3]),                 \
      "r"((b)[0]), "r"((b)[1]))

static __device__ __forceinline__ uint32_t tf32_bits(float a) {
    uint32_t r;
    asm("cvt.rna.tf32.f32 %0, %1;" : "=r"(r) : "f"(a));
    return r;
}

__global__ __launch_bounds__(NTHREADS)
void router_mma_kernel(const float* __restrict__ x, const float* __restrict__ Wg,
                       float* __restrict__ w_out, float* __restrict__ i_out,
                       float* __restrict__ l_out)
{
    extern __shared__ float sm[];
    uint32_t* smu = (uint32_t*)sm;

    const int tid = threadIdx.x;
    const int wid = tid >> 5;
    const int lid = tid & 31;
    const int g   = lid >> 2;
    const int t   = lid & 3;
    const int wm  = wid >> 1;      // 0..1 : 32-token slab
    const int wn  = wid & 1;       // 0..1 : 32-expert slab
    const int t0  = blockIdx.x * BM;

    float c[2][4][4];
    #pragma unroll
    for (int i = 0; i < 2; i++)
        #pragma unroll
        for (int j = 0; j < 4; j++)
            #pragma unroll
            for (int k = 0; k < 4; k++) c[i][j][k] = 0.0f;

    const float4* xg = (const float4*)(x + (size_t)t0 * DMODEL);
    const float4* wg = (const float4*)Wg;

    // per chunk: x = 64 rows x 8 float4 = 512 float4 -> 4/thread; W same
    float4 xr[4], wr[4];
    #pragma unroll
    for (int p = 0; p < 4; p++) {
        int id = tid + 128 * p;
        xr[p] = xg[(size_t)(id >> 3) * (DMODEL / 4) + (id & 7)];
        wr[p] = wg[(size_t)(id >> 3) * (DMODEL / 4) + (id & 7)];
    }

    for (int ck = 0; ck < NCHUNK; ck++) {
        const int bo = (ck & 1) * SBUF;

        // ---- split hi/lo + stage into buffer (conflict-free STS.128) ----
        #pragma unroll
        for (int p = 0; p < 4; p++) {
            int id = tid + 128 * p;
            int r = id >> 3, q = id & 7;
            float4 v = xr[p], h, l;
            h.x = __uint_as_float(tf32_bits(v.x)); l.x = __uint_as_float(tf32_bits(v.x - h.x));
            h.y = __uint_as_float(tf32_bits(v.y)); l.y = __uint_as_float(tf32_bits(v.y - h.y));
            h.z = __uint_as_float(tf32_bits(v.z)); l.z = __uint_as_float(tf32_bits(v.z - h.z));
            h.w = __uint_as_float(tf32_bits(v.w)); l.w = __uint_as_float(tf32_bits(v.w - h.w));
            *(float4*)&sm[bo + r * XPITCH + q * 4]           = h;
            *(float4*)&sm[bo + TSZ + r * XPITCH + q * 4]     = l;
            float4 wv = wr[p], wh, wl;
            wh.x = __uint_as_float(tf32_bits(wv.x)); wl.x = __uint_as_float(tf32_bits(wv.x - wh.x));
            wh.y = __uint_as_float(tf32_bits(wv.y)); wl.y = __uint_as_float(tf32_bits(wv.y - wh.y));
            wh.z = __uint_as_float(tf32_bits(wv.z)); wl.z = __uint_as_float(tf32_bits(wv.z - wh.z));
            wh.w = __uint_as_float(tf32_bits(wv.w)); wl.w = __uint_as_float(tf32_bits(wv.w - wh.w));
            *(float4*)&sm[bo + 2 * TSZ + r * XPITCH + q * 4] = wh;
            *(float4*)&sm[bo + 3 * TSZ + r * XPITCH + q * 4] = wl;
        }
        __syncthreads();    // single barrier per chunk (double-buffered)

        // ---- prefetch next chunk (overlaps MMAs) ----
        if (ck + 1 < NCHUNK) {
            const int kq = (ck + 1) * (KC / 4);
            #pragma unroll
            for (int p = 0; p < 4; p++) {
                int id = tid + 128 * p;
                xr[p] = xg[(size_t)(id >> 3) * (DMODEL / 4) + kq + (id & 7)];
                wr[p] = wg[(size_t)(id >> 3) * (DMODEL / 4) + kq + (id & 7)];
            }
        }

        // ---- 4 k8-slices: 3 passes (hh, hl, lh) ----
        #pragma unroll
        for (int s = 0; s < 4; s++) {
            uint32_t ah[2][4], al[2][4], bh[4][2], bl[4][2];
            const int cc = s * 8 + t;
            #pragma unroll
            for (int mt = 0; mt < 2; mt++) {
                const int r0 = wm * 32 + mt * 16 + g;
                ah[mt][0] = smu[bo + r0 * XPITCH + cc];
                ah[mt][1] = smu[bo + (r0 + 8) * XPITCH + cc];
                ah[mt][2] = smu[bo + r0 * XPITCH + cc + 4];
                ah[mt][3] = smu[bo + (r0 + 8) * XPITCH + cc + 4];
                al[mt][0] = smu[bo + TSZ + r0 * XPITCH + cc];
                al[mt][1] = smu[bo + TSZ + (r0 + 8) * XPITCH + cc];
                al[mt][2] = smu[bo + TSZ + r0 * XPITCH + cc + 4];
                al[mt][3] = smu[bo + TSZ + (r0 + 8) * XPITCH + cc + 4];
            }
            #pragma unroll
            for (int nt = 0; nt < 4; nt++) {
                const int e0 = wn * 32 + nt * 8 + g;
                bh[nt][0] = smu[bo + 2 * TSZ + e0 * XPITCH + cc];
                bh[nt][1] = smu[bo + 2 * TSZ + e0 * XPITCH + cc + 4];
                bl[nt][0] = smu[bo + 3 * TSZ + e0 * XPITCH + cc];
                bl[nt][1] = smu[bo + 3 * TSZ + e0 * XPITCH + cc + 4];
            }
            #pragma unroll
            for (int mt = 0; mt < 2; mt++)
                #pragma unroll
                for (int nt = 0; nt < 4; nt++) {
                    MMA(c[mt][nt], ah[mt], bh[nt]);
                    MMA(c[mt][nt], ah[mt], bl[nt]);
                    MMA(c[mt][nt], al[mt], bh[nt]);
                }
        }
    }
    __syncthreads();

    // ---- epilogue: accums -> smem logits [64][65] (fits in buffer 0) ----
    float* L = sm;
    #pragma unroll
    for (int mt = 0; mt < 2; mt++) {
        const int row = wm * 32 + mt * 16 + g;
        #pragma unroll
        for (int nt = 0; nt < 4; nt++) {
            const int col = wn * 32 + nt * 8 + 2 * t;
            L[row * LPITCH + col]           = c[mt][nt][0];
            L[row * LPITCH + col + 1]       = c[mt][nt][1];
            L[(row + 8) * LPITCH + col]     = c[mt][nt][2];
            L[(row + 8) * LPITCH + col + 1] = c[mt][nt][3];
        }
    }
    __syncthreads();

    // ---- per-token top-4 + near-tie fp64 rescue + softmax (warps 0,1) ----
    if (tid < BM) {
        const float* row = &L[tid * LPITCH];
        float v1 = -INFINITY, v2 = -INFINITY, v3 = -INFINITY, v4 = -INFINITY;
        int   i1 = 0, i2 = 0, i3 = 0, i4 = 0;
        #pragma unroll 8
        for (int e = 0; e < NEXP; e++) {
            float v = row[e];
            if (v > v1)      { v4=v3;i4=i3; v3=v2;i3=i2; v2=v1;i2=i1; v1=v;i1=e; }
            else if (v > v2) { v4=v3;i4=i3; v3=v2;i3=i2; v2=v;i2=e; }
            else if (v > v3) { v4=v3;i4=i3; v3=v;i3=e; }
            else if (v > v4) { v4=v;i4=e; }
        }

        const bool flagged = (v1 - v2 < THR) || (v2 - v3 < THR);
        unsigned m = __ballot_sync(0xffffffffu, flagged);
        while (m) {
            const int src = __ffs(m) - 1;
            m &= m - 1;
            const int tok = t0 + (tid & ~31) + src;
            int cand[4];
            cand[0] = __shfl_sync(0xffffffffu, i1, src);
            cand[1] = __shfl_sync(0xffffffffu, i2, src);
            cand[2] = __shfl_sync(0xffffffffu, i3, src);
            cand[3] = __shfl_sync(0xffffffffu, i4, src);

            const int slot = lid >> 3;
            const int kl   = lid & 7;
            const int e    = cand[slot];
            const float* xp = x  + (size_t)tok * DMODEL;
            const float* wp = Wg + (size_t)e   * DMODEL;

            double a0 = 0.0, a1 = 0.0, a2 = 0.0, a3 = 0.0;
            #pragma unroll 4
            for (int j = 0; j < 256; j += 4) {
                int k0 = (j + 0) * 8 + kl;
                int k1 = (j + 1) * 8 + kl;
                int k2 = (j + 2) * 8 + kl;
                int k3 = (j + 3) * 8 + kl;
                a0 = fma((double)xp[k0], (double)wp[k0], a0);
                a1 = fma((double)xp[k1], (double)wp[k1], a1);
                a2 = fma((double)xp[k2], (double)wp[k2], a2);
                a3 = fma((double)xp[k3], (double)wp[k3], a3);
            }
            double tot = (a0 + a1) + (a2 + a3);
            tot += __shfl_xor_sync(0xffffffffu, tot, 4);
            tot += __shfl_xor_sync(0xffffffffu, tot, 2);
            tot += __shfl_xor_sync(0xffffffffu, tot, 1);

            double gv[4];
            gv[0] = __shfl_sync(0xffffffffu, tot, 0);
            gv[1] = __shfl_sync(0xffffffffu, tot, 8);
            gv[2] = __shfl_sync(0xffffffffu, tot, 16);
            gv[3] = __shfl_sync(0xffffffffu, tot, 24);

            if (lid == src) {
                int o1 = 0;
                #pragma unroll
                for (int s = 1; s < 4; s++)
                    if (gv[s] > gv[o1] || (gv[s] == gv[o1] && cand[s] < cand[o1])) o1 = s;
                int o2 = (o1 == 0) ? 1 : 0;
                #pragma unroll
                for (int s = 0; s < 4; s++) {
                    if (s == o1 || s == o2) continue;
                    if (gv[s] > gv[o2] || (gv[s] == gv[o2] && cand[s] < cand[o2])) o2 = s;
                }
                i1 = cand[o1]; i2 = cand[o2];
                v1 = row[i1];  v2 = row[i2];
            }
        }

        float S = 0.0f;
        #pragma unroll 8
        for (int e = 0; e < NEXP; e++) S += expf(row[e] - v1);
        const float p1  = expf(row[i1] - v1) / S;
        const float p2  = expf(v2 - v1) / S;
        const float inv = 1.0f / (p1 + p2 + 1e-10f);
        const size_t n = (size_t)(t0 + tid);
        w_out[2 * n]     = p1 * inv;
        w_out[2 * n + 1] = p2 * inv;
        i_out[2 * n]     = (float)i1;
        i_out[2 * n + 1] = (float)i2;
    }

    // coalesced logits store: 64x64 = 1024 float4 -> 8/thread
    #pragma unroll
    for (int p = 0; p < 8; p++) {
        int id = tid + 128 * p;
        int rr = id >> 4, q = id & 15;
        float4 v;
        v.x = L[rr * LPITCH + 4 * q];
        v.y = L[rr * LPITCH + 4 * q + 1];
        v.z = L[rr * LPITCH + 4 * q + 2];
        v.w = L[rr * LPITCH + 4 * q + 3];
        *(float4*)(l_out + (size_t)(t0 + rr) * NEXP + 4 * q) = v;
    }
}

extern "C" void kernel_launch(void* const* d_in, const int* in_sizes, int n_in,
                              void* d_out, int out_size)
{
    const float* x  = (const float*)d_in[0];
    const float* Wg = (const float*)d_in[1];
    const int N = in_sizes[0] / DMODEL;       // 16384

    float* out   = (float*)d_out;
    float* w_out = out;
    float* i_out = out + (size_t)N * 2;
    float* l_out = out + (size_t)N * 4;

    cudaFuncSetAttribute(router_mma_kernel,
                         cudaFuncAttributeMaxDynamicSharedMemorySize, SMEM_BYTES);
    router_mma_kernel<<<N / BM, NTHREADS, SMEM_BYTES>>>(x, Wg, w_out, i_out, l_out);
}

// round 8
// speedup vs baseline: 2.1859x; 1.3737x over previous
#include <cuda_runtime.h>
#include <math.h>
#include <stdint.h>

// TopKRouter: 3-pass BF16 split GEMM via mma.sync m16n8k16 + ldmatrix,
// fp64 rescue for near-tied top-2 decisions.
// logits = x @ W^T ~= xh@wh + xh@wl + xl@wh  (bf16 hi/lo split, err ~5e-6 abs)
// N=16384, D=2048, E=64. Output: [0,2N) weights | [2N,4N) idx | [4N,68N) logits

#define DMODEL   2048
#define NEXP     64
#define BM       64
#define KC       32
#define NCHUNK   (DMODEL / KC)      // 64
#define NTHREADS 128
#define LPITCH   65
#define THR      5e-4f

// bf16 tiles: 64 rows x 32 bf16 (64 B data), pitch 80 B (conflict-free)
#define P     80
#define TILE  (64 * P)              // 5120 B
#define XH_T  0
#define XL_T  TILE
#define WH_T  (2 * TILE)
#define WL_T  (3 * TILE)
#define SBUF  (4 * TILE)            // 20480 B per buffer
#define SMEM_BYTES (2 * SBUF)       // 40960 B

#define MMAB(c, a, b0, b1) asm volatile(                                  \
    "mma.sync.aligned.m16n8k16.row.col.f32.bf16.bf16.f32 "                \
    "{%0,%1,%2,%3}, {%4,%5,%6,%7}, {%8,%9}, {%0,%1,%2,%3};"               \
    : "+f"((c)[0]), "+f"((c)[1]), "+f"((c)[2]), "+f"((c)[3])              \
    : "r"((a)[0]), "r"((a)[1]), "r"((a)[2]), "r"((a)[3]),                 \
      "r"(b0), "r"(b1))

#define LDM4(r, addr) asm volatile(                                       \
    "ldmatrix.sync.aligned.m8n8.x4.shared.b16 {%0,%1,%2,%3}, [%4];"       \
    : "=r"((r)[0]), "=r"((r)[1]), "=r"((r)[2]), "=r"((r)[3]) : "r"(addr))

#define STS64(addr, u0, u1) asm volatile(                                 \
    "st.shared.v2.u32 [%0], {%1,%2};" :: "r"(addr), "r"(u0), "r"(u1) : "memory")

static __device__ __forceinline__ void bsplit(float4 v, uint32_t& h0, uint32_t& h1,
                                              uint32_t& l0, uint32_t& l1) {
    asm("cvt.rn.bf16x2.f32 %0, %1, %2;" : "=r"(h0) : "f"(v.y), "f"(v.x));
    asm("cvt.rn.bf16x2.f32 %0, %1, %2;" : "=r"(h1) : "f"(v.w), "f"(v.z));
    float f0 = __uint_as_float(h0 << 16);
    float f1 = __uint_as_float(h0 & 0xffff0000u);
    float f2 = __uint_as_float(h1 << 16);
    float f3 = __uint_as_float(h1 & 0xffff0000u);
    asm("cvt.rn.bf16x2.f32 %0, %1, %2;" : "=r"(l0) : "f"(v.y - f1), "f"(v.x - f0));
    asm("cvt.rn.bf16x2.f32 %0, %1, %2;" : "=r"(l1) : "f"(v.w - f3), "f"(v.z - f2));
}

__global__ __launch_bounds__(NTHREADS)
void router_mma_kernel(const float* __restrict__ x, const float* __restrict__ Wg,
                       float* __restrict__ w_out, float* __restrict__ i_out,
                       float* __restrict__ l_out)
{
    extern __shared__ __align__(16) char smc[];
    float* sm = (float*)smc;
    uint32_t sb;
    asm("{ .reg .u64 t; cvta.to.shared.u64 t, %1; cvt.u32.u64 %0, t; }" : "=r"(sb) : "l"(smc));

    const int tid = threadIdx.x;
    const int wid = tid >> 5;
    const int lid = tid & 31;
    const int g   = lid >> 2;
    const int t   = lid & 3;
    const int wm  = wid >> 1;      // 0..1 : 32-token slab
    const int wn  = wid & 1;       // 0..1 : 32-expert slab
    const int t0  = blockIdx.x * BM;

    float c[2][4][4];
    #pragma unroll
    for (int i = 0; i < 2; i++)
        #pragma unroll
        for (int j = 0; j < 4; j++)
            #pragma unroll
            for (int k = 0; k < 4; k++) c[i][j][k] = 0.0f;

    const float4* xg = (const float4*)(x + (size_t)t0 * DMODEL);
    const float4* wg = (const float4*)Wg;

    float4 xr[4], wr[4];
    #pragma unroll
    for (int p = 0; p < 4; p++) {
        int id = tid + 128 * p;
        xr[p] = xg[(size_t)(id >> 3) * (DMODEL / 4) + (id & 7)];
        wr[p] = wg[(size_t)(id >> 3) * (DMODEL / 4) + (id & 7)];
    }

    // ldmatrix per-lane address components (byte offsets within a tile)
    const uint32_t a_off = (uint32_t)(wm * 32 + (lid & 15)) * P + (lid >> 4) * 16;
    const uint32_t b_off = (uint32_t)(wn * 32 + (lid & 7) + ((lid >> 4) & 1) * 8) * P
                         + ((lid >> 3) & 1) * 16;

    for (int ck = 0; ck < NCHUNK; ck++) {
        const uint32_t bo = sb + (ck & 1) * SBUF;

        // ---- split + stage (STS.64, rows 64B data / 80B pitch) ----
        #pragma unroll
        for (int p = 0; p < 4; p++) {
            int id = tid + 128 * p;
            uint32_t ad = (uint32_t)(id >> 3) * P + (uint32_t)(id & 7) * 8;
            uint32_t h0, h1, l0, l1;
            bsplit(xr[p], h0, h1, l0, l1);
            STS64(bo + XH_T + ad, h0, h1);
            STS64(bo + XL_T + ad, l0, l1);
            bsplit(wr[p], h0, h1, l0, l1);
            STS64(bo + WH_T + ad, h0, h1);
            STS64(bo + WL_T + ad, l0, l1);
        }
        __syncthreads();    // single barrier per chunk (double-buffered)

        // ---- prefetch next chunk ----
        if (ck + 1 < NCHUNK) {
            const int kq = (ck + 1) * (KC / 4);
            #pragma unroll
            for (int p = 0; p < 4; p++) {
                int id = tid + 128 * p;
                xr[p] = xg[(size_t)(id >> 3) * (DMODEL / 4) + kq + (id & 7)];
                wr[p] = wg[(size_t)(id >> 3) * (DMODEL / 4) + kq + (id & 7)];
            }
        }

        // ---- 2 k16-slices, 3 passes (hh, hl, lh) ----
        #pragma unroll
        for (int s = 0; s < 2; s++) {
            const uint32_t so = s * 32;          // 16 bf16 = 32 B per slice
            uint32_t ah[2][4], al[2][4], bh[2][4], bl[2][4];
            #pragma unroll
            for (int mt = 0; mt < 2; mt++) {
                LDM4(ah[mt], bo + XH_T + a_off + mt * 16 * P + so);
                LDM4(al[mt], bo + XL_T + a_off + mt * 16 * P + so);
            }
            #pragma unroll
            for (int bp = 0; bp < 2; bp++) {     // expert pair-tiles (16 experts)
                LDM4(bh[bp], bo + WH_T + b_off + bp * 16 * P + so);
                LDM4(bl[bp], bo + WL_T + b_off + bp * 16 * P + so);
            }
            #pragma unroll
            for (int mt = 0; mt < 2; mt++)
                #pragma unroll
                for (int nt = 0; nt < 4; nt++) {
                    const int bp = nt >> 1, hv = (nt & 1) * 2;
                    MMAB(c[mt][nt], ah[mt], bh[bp][hv], bh[bp][hv + 1]);
                    MMAB(c[mt][nt], ah[mt], bl[bp][hv], bl[bp][hv + 1]);
                    MMAB(c[mt][nt], al[mt], bh[bp][hv], bh[bp][hv + 1]);
                }
        }
    }
    __syncthreads();

    // ---- epilogue: accums -> smem logits [64][65] ----
    float* L = sm;
    #pragma unroll
    for (int mt = 0; mt < 2; mt++) {
        const int row = wm * 32 + mt * 16 + g;
        #pragma unroll
        for (int nt = 0; nt < 4; nt++) {
            const int col = wn * 32 + nt * 8 + 2 * t;
            L[row * LPITCH + col]           = c[mt][nt][0];
            L[row * LPITCH + col + 1]       = c[mt][nt][1];
            L[(row + 8) * LPITCH + col]     = c[mt][nt][2];
            L[(row + 8) * LPITCH + col + 1] = c[mt][nt][3];
        }
    }
    __syncthreads();

    // ---- per-token top-4 + near-tie fp64 rescue + softmax (warps 0,1) ----
    if (tid < BM) {
        const float* row = &L[tid * LPITCH];
        float v1 = -INFINITY, v2 = -INFINITY, v3 = -INFINITY, v4 = -INFINITY;
        int   i1 = 0, i2 = 0, i3 = 0, i4 = 0;
        #pragma unroll 8
        for (int e = 0; e < NEXP; e++) {
            float v = row[e];
            if (v > v1)      { v4=v3;i4=i3; v3=v2;i3=i2; v2=v1;i2=i1; v1=v;i1=e; }
            else if (v > v2) { v4=v3;i4=i3; v3=v2;i3=i2; v2=v;i2=e; }
            else if (v > v3) { v4=v3;i4=i3; v3=v;i3=e; }
            else if (v > v4) { v4=v;i4=e; }
        }

        const bool flagged = (v1 - v2 < THR) || (v2 - v3 < THR);
        unsigned m = __ballot_sync(0xffffffffu, flagged);
        while (m) {
            const int src = __ffs(m) - 1;
            m &= m - 1;
            const int tok = t0 + (tid & ~31) + src;
            int cand[4];
            cand[0] = __shfl_sync(0xffffffffu, i1, src);
            cand[1] = __shfl_sync(0xffffffffu, i2, src);
            cand[2] = __shfl_sync(0xffffffffu, i3, src);
            cand[3] = __shfl_sync(0xffffffffu, i4, src);

            const int slot = lid >> 3;
            const int kl   = lid & 7;
            const int e    = cand[slot];
            const float* xp = x  + (size_t)tok * DMODEL;
            const float* wp = Wg + (size_t)e   * DMODEL;

            double a0 = 0.0, a1 = 0.0, a2 = 0.0, a3 = 0.0;
            #pragma unroll 4
            for (int j = 0; j < 256; j += 4) {
                int k0 = (j + 0) * 8 + kl;
                int k1 = (j + 1) * 8 + kl;
                int k2 = (j + 2) * 8 + kl;
                int k3 = (j + 3) * 8 + kl;
                a0 = fma((double)xp[k0], (double)wp[k0], a0);
                a1 = fma((double)xp[k1], (double)wp[k1], a1);
                a2 = fma((double)xp[k2], (double)wp[k2], a2);
                a3 = fma((double)xp[k3], (double)wp[k3], a3);
            }
            double tot = (a0 + a1) + (a2 + a3);
            tot += __shfl_xor_sync(0xffffffffu, tot, 4);
            tot += __shfl_xor_sync(0xffffffffu, tot, 2);
            tot += __shfl_xor_sync(0xffffffffu, tot, 1);

            double gv[4];
            gv[0] = __shfl_sync(0xffffffffu, tot, 0);
            gv[1] = __shfl_sync(0xffffffffu, tot, 8);
            gv[2] = __shfl_sync(0xffffffffu, tot, 16);
            gv[3] = __shfl_sync(0xffffffffu, tot, 24);

            if (lid == src) {
                int o1 = 0;
                #pragma unroll
                for (int s = 1; s < 4; s++)
                    if (gv[s] > gv[o1] || (gv[s] == gv[o1] && cand[s] < cand[o1])) o1 = s;
                int o2 = (o1 == 0) ? 1 : 0;
                #pragma unroll
                for (int s = 0; s < 4; s++) {
                    if (s == o1 || s == o2) continue;
                    if (gv[s] > gv[o2] || (gv[s] == gv[o2] && cand[s] < cand[o2])) o2 = s;
                }
                i1 = cand[o1]; i2 = cand[o2];
                v1 = row[i1];  v2 = row[i2];
            }
        }

        float S = 0.0f;
        #pragma unroll 8
        for (int e = 0; e < NEXP; e++) S += expf(row[e] - v1);
        const float p1  = expf(row[i1] - v1) / S;
        const float p2  = expf(v2 - v1) / S;
        const float inv = 1.0f / (p1 + p2 + 1e-10f);
        const size_t n = (size_t)(t0 + tid);
        w_out[2 * n]     = p1 * inv;
        w_out[2 * n + 1] = p2 * inv;
        i_out[2 * n]     = (float)i1;
        i_out[2 * n + 1] = (float)i2;
    }

    // coalesced logits store
    #pragma unroll
    for (int p = 0; p < 8; p++) {
        int id = tid + 128 * p;
        int rr = id >> 4, q = id & 15;
        float4 v;
        v.x = L[rr * LPITCH + 4 * q];
        v.y = L[rr * LPITCH + 4 * q + 1];
        v.z = L[rr * LPITCH + 4 * q + 2];
        v.w = L[rr * LPITCH + 4 * q + 3];
        *(float4*)(l_out + (size_t)(t0 + rr) * NEXP + 4 * q) = v;
    }
}

extern "C" void kernel_launch(void* const* d_in, const int* in_sizes, int n_in,
                              void* d_out, int out_size)
{
    const float* x  = (const float*)d_in[0];
    const float* Wg = (const float*)d_in[1];
    const int N = in_sizes[0] / DMODEL;       // 16384

    float* out   = (float*)d_out;
    float* w_out = out;
    float* i_out = out + (size_t)N * 2;
    float* l_out = out + (size_t)N * 4;

    cudaFuncSetAttribute(router_mma_kernel,
                         cudaFuncAttributeMaxDynamicSharedMemorySize, SMEM_BYTES);
    router_mma_kernel<<<N / BM, NTHREADS, SMEM_BYTES>>>(x, Wg, w_out, i_out, l_out);
}

// round 9
// speedup vs baseline: 2.4574x; 1.1242x over previous
#include <cuda_runtime.h>
#include <cuda_bf16.h>
#include <math.h>
#include <stdint.h>

// TopKRouter: 3-pass BF16 split GEMM, warp-level K-split (4 slices),
// W pre-split to bf16 hi/lo in global, fp64 rescue for near-tied top-2.
// N=16384, D=2048, E=64. Output: [0,2N) weights | [2N,4N) idx | [4N,68N) logits

#define DMODEL   2048
#define NEXP     64
#define BM       64
#define KC       64                  // floats per chunk
#define NCHUNK   (DMODEL / KC)       // 32
#define NTHREADS 128
#define LPITCH   65
#define THR      5e-4f

// staging tiles: 64 rows x 64 bf16 (128 B data), pitch 144 B (conflict-free)
#define P2    144
#define TILE2 (64 * P2)              // 9216 B
#define XH_T  0
#define XL_T  TILE2
#define WH_T  (2 * TILE2)
#define WL_T  (3 * TILE2)
#define SBUF  (4 * TILE2)            // 36864 B
#define SMEM_BYTES (2 * SBUF)        // 73728 B

__device__ uint4 g_wh4[NEXP * DMODEL / 8];   // W hi, bf16 [64][2048]
__device__ uint4 g_wl4[NEXP * DMODEL / 8];   // W lo

#define MMAB(c, a, b0, b1) asm volatile(                                  \
    "mma.sync.aligned.m16n8k16.row.col.f32.bf16.bf16.f32 "                \
    "{%0,%1,%2,%3}, {%4,%5,%6,%7}, {%8,%9}, {%0,%1,%2,%3};"               \
    : "+f"((c)[0]), "+f"((c)[1]), "+f"((c)[2]), "+f"((c)[3])              \
    : "r"((a)[0]), "r"((a)[1]), "r"((a)[2]), "r"((a)[3]),                 \
      "r"(b0), "r"(b1))

#define LDM4(r, addr) asm volatile(                                       \
    "ldmatrix.sync.aligned.m8n8.x4.shared.b16 {%0,%1,%2,%3}, [%4];"       \
    : "=r"((r)[0]), "=r"((r)[1]), "=r"((r)[2]), "=r"((r)[3]) : "r"(addr))

#define STS64(addr, u0, u1) asm volatile(                                 \
    "st.shared.v2.u32 [%0], {%1,%2};" :: "r"(addr), "r"(u0), "r"(u1) : "memory")
#define STS128(addr, v) asm volatile(                                     \
    "st.shared.v4.u32 [%0], {%1,%2,%3,%4};"                               \
    :: "r"(addr), "r"((v).x), "r"((v).y), "r"((v).z), "r"((v).w) : "memory")

static __device__ __forceinline__ void bsplit(float4 v, uint32_t& h0, uint32_t& h1,
                                              uint32_t& l0, uint32_t& l1) {
    asm("cvt.rn.bf16x2.f32 %0, %1, %2;" : "=r"(h0) : "f"(v.y), "f"(v.x));
    asm("cvt.rn.bf16x2.f32 %0, %1, %2;" : "=r"(h1) : "f"(v.w), "f"(v.z));
    float f0 = __uint_as_float(h0 << 16);
    float f1 = __uint_as_float(h0 & 0xffff0000u);
    float f2 = __uint_as_float(h1 << 16);
    float f3 = __uint_as_float(h1 & 0xffff0000u);
    asm("cvt.rn.bf16x2.f32 %0, %1, %2;" : "=r"(l0) : "f"(v.y - f1), "f"(v.x - f0));
    asm("cvt.rn.bf16x2.f32 %0, %1, %2;" : "=r"(l1) : "f"(v.w - f3), "f"(v.z - f2));
}

// ---- pre-kernel: split W into bf16 hi/lo (runs once, ~512 KB traffic) ----
__global__ void wsplit_kernel(const float* __restrict__ Wg) {
    const int i = blockIdx.x * 256 + threadIdx.x;       // 16384 threads, 8 elems each
    const float4* w4 = (const float4*)Wg;
    float4 a = w4[2 * i], b = w4[2 * i + 1];
    uint4 h, l;
    bsplit(a, h.x, h.y, l.x, l.y);
    bsplit(b, h.z, h.w, l.z, l.w);
    g_wh4[i] = h;
    g_wl4[i] = l;
}

__global__ __launch_bounds__(NTHREADS, 2)
void router_mma_kernel(const float* __restrict__ x, const float* __restrict__ Wg,
                       float* __restrict__ w_out, float* __restrict__ i_out,
                       float* __restrict__ l_out)
{
    extern __shared__ __align__(16) char smc[];
    float* sm = (float*)smc;
    uint32_t sb;
    asm("{ .reg .u64 t; cvta.to.shared.u64 t, %1; cvt.u32.u64 %0, t; }" : "=r"(sb) : "l"(smc));

    const int tid = threadIdx.x;
    const int wid = tid >> 5;      // warp = k16-slice id 0..3
    const int lid = tid & 31;
    const int g   = lid >> 2;
    const int t   = lid & 3;
    const int t0  = blockIdx.x * BM;

    float c[4][8][4];              // full 64x64 tile per warp (K-split partial)
    #pragma unroll
    for (int i = 0; i < 4; i++)
        #pragma unroll
        for (int j = 0; j < 8; j++)
            #pragma unroll
            for (int k = 0; k < 4; k++) c[i][j][k] = 0.0f;

    const float4* xg = (const float4*)(x + (size_t)t0 * DMODEL);

    // x prefetch: 64 rows x 16 float4 = 1024 float4 -> 8/thread
    float4 xr[8];
    #pragma unroll
    for (int p = 0; p < 8; p++) {
        int id = tid + 128 * p;
        xr[p] = xg[(size_t)(id >> 4) * (DMODEL / 4) + (id & 15)];
    }

    // per-lane ldmatrix byte offsets (within a tile, pitch P2)
    const uint32_t a_base = (uint32_t)(lid & 15) * P2 + (lid >> 4) * 16 + wid * 32;
    const uint32_t b_base = (uint32_t)((lid & 7) + ((lid >> 4) & 1) * 8) * P2
                          + ((lid >> 3) & 1) * 16 + wid * 32;

    #pragma unroll 1
    for (int ck = 0; ck < NCHUNK; ck++) {
        const uint32_t bo = sb + (ck & 1) * SBUF;

        // ---- W tile loads (bf16, L2-hot): 4+4 uint4/thread ----
        uint4 whr[4], wlr[4];
        #pragma unroll
        for (int p = 0; p < 4; p++) {
            int id = tid + 128 * p;                      // 512 uint4 per tile
            int gi = (id >> 3) * (DMODEL / 8) + ck * 8 + (id & 7);
            whr[p] = g_wh4[gi];
            wlr[p] = g_wl4[gi];
        }

        // ---- x split + stage (overlaps W LDG latency) ----
        #pragma unroll
        for (int p = 0; p < 8; p++) {
            int id = tid + 128 * p;
            uint32_t ad = (uint32_t)(id >> 4) * P2 + (uint32_t)(id & 15) * 8;
            uint32_t h0, h1, l0, l1;
            bsplit(xr[p], h0, h1, l0, l1);
            STS64(bo + XH_T + ad, h0, h1);
            STS64(bo + XL_T + ad, l0, l1);
        }
        // ---- W stage ----
        #pragma unroll
        for (int p = 0; p < 4; p++) {
            int id = tid + 128 * p;
            uint32_t ad = (uint32_t)(id >> 3) * P2 + (uint32_t)(id & 7) * 16;
            STS128(bo + WH_T + ad, whr[p]);
            STS128(bo + WL_T + ad, wlr[p]);
        }
        __syncthreads();    // single barrier per chunk (double-buffered)

        // ---- prefetch next x chunk (overlaps MMAs) ----
        if (ck + 1 < NCHUNK) {
            const int kq = (ck + 1) * (KC / 4);
            #pragma unroll
            for (int p = 0; p < 8; p++) {
                int id = tid + 128 * p;
                xr[p] = xg[(size_t)(id >> 4) * (DMODEL / 4) + kq + (id & 15)];
            }
        }

        // ---- this warp's k16 slice: 96 MMAs (3 passes x 4mt x 8nt) ----
        uint32_t bh[4][4], bl[4][4];
        #pragma unroll
        for (int bp = 0; bp < 4; bp++) {
            uint32_t ba = bo + WH_T + b_base + bp * 16 * P2;
            LDM4(bh[bp], ba);
            LDM4(bl[bp], ba + (WL_T - WH_T));
        }
        #pragma unroll
        for (int mt = 0; mt < 4; mt++) {
            uint32_t ah[4], al[4];
            uint32_t aa = bo + XH_T + a_base + mt * 16 * P2;
            LDM4(ah, aa);
            LDM4(al, aa + TILE2);
            #pragma unroll
            for (int bp = 0; bp < 4; bp++)
                #pragma unroll
                for (int sub = 0; sub < 2; sub++) {
                    const int nt = bp * 2 + sub;
                    MMAB(c[mt][nt], ah, bh[bp][2*sub], bh[bp][2*sub + 1]);
                    MMAB(c[mt][nt], ah, bl[bp][2*sub], bl[bp][2*sub + 1]);
                    MMAB(c[mt][nt], al, bh[bp][2*sub], bh[bp][2*sub + 1]);
                }
        }
    }
    __syncthreads();

    // ---- epilogue: each warp stores its K-partial tile [64][65] ----
    {
        float* Pw = sm + wid * (64 * LPITCH);
        #pragma unroll
        for (int mt = 0; mt < 4; mt++) {
            const int row = 16 * mt + g;
            #pragma unroll
            for (int nt = 0; nt < 8; nt++) {
                const int col = 8 * nt + 2 * t;
                Pw[row * LPITCH + col]           = c[mt][nt][0];
                Pw[row * LPITCH + col + 1]       = c[mt][nt][1];
                Pw[(row + 8) * LPITCH + col]     = c[mt][nt][2];
                Pw[(row + 8) * LPITCH + col + 1] = c[mt][nt][3];
            }
        }
    }
    __syncthreads();

    // ---- reduce 4 partials into warp-0 area (in place, per element) ----
    float* L = sm;
    #pragma unroll
    for (int j = 0; j < 32; j++) {
        int idx = tid + 128 * j;                  // 4096 elements
        int addr = (idx >> 6) * LPITCH + (idx & 63);
        L[addr] = (L[addr] + sm[64 * LPITCH + addr])
                + (sm[128 * LPITCH + addr] + sm[192 * LPITCH + addr]);
    }
    __syncthreads();

    // ---- per-token top-4 + near-tie fp64 rescue + softmax (warps 0,1) ----
    if (tid < BM) {
        const float* row = &L[tid * LPITCH];
        float v1 = -INFINITY, v2 = -INFINITY, v3 = -INFINITY, v4 = -INFINITY;
        int   i1 = 0, i2 = 0, i3 = 0, i4 = 0;
        #pragma unroll 8
        for (int e = 0; e < NEXP; e++) {
            float v = row[e];
            if (v > v1)      { v4=v3;i4=i3; v3=v2;i3=i2; v2=v1;i2=i1; v1=v;i1=e; }
            else if (v > v2) { v4=v3;i4=i3; v3=v2;i3=i2; v2=v;i2=e; }
            else if (v > v3) { v4=v3;i4=i3; v3=v;i3=e; }
            else if (v > v4) { v4=v;i4=e; }
        }

        const bool flagged = (v1 - v2 < THR) || (v2 - v3 < THR);
        unsigned m = __ballot_sync(0xffffffffu, flagged);
        while (m) {
            const int src = __ffs(m) - 1;
            m &= m - 1;
            const int tok = t0 + (tid & ~31) + src;
            int cand[4];
            cand[0] = __shfl_sync(0xffffffffu, i1, src);
            cand[1] = __shfl_sync(0xffffffffu, i2, src);
            cand[2] = __shfl_sync(0xffffffffu, i3, src);
            cand[3] = __shfl_sync(0xffffffffu, i4, src);

            const int slot = lid >> 3;
            const int kl   = lid & 7;
            const int e    = cand[slot];
            const float* xp = x  + (size_t)tok * DMODEL;
            const float* wp = Wg + (size_t)e   * DMODEL;

            double a0 = 0.0, a1 = 0.0, a2 = 0.0, a3 = 0.0;
            #pragma unroll 4
            for (int j = 0; j < 256; j += 4) {
                int k0 = (j + 0) * 8 + kl;
                int k1 = (j + 1) * 8 + kl;
                int k2 = (j + 2) * 8 + kl;
                int k3 = (j + 3) * 8 + kl;
                a0 = fma((double)xp[k0], (double)wp[k0], a0);
                a1 = fma((double)xp[k1], (double)wp[k1], a1);
                a2 = fma((double)xp[k2], (double)wp[k2], a2);
                a3 = fma((double)xp[k3], (double)wp[k3], a3);
            }
            double tot = (a0 + a1) + (a2 + a3);
            tot += __shfl_xor_sync(0xffffffffu, tot, 4);
            tot += __shfl_xor_sync(0xffffffffu, tot, 2);
            tot += __shfl_xor_sync(0xffffffffu, tot, 1);

            double gv[4];
            gv[0] = __shfl_sync(0xffffffffu, tot, 0);
            gv[1] = __shfl_sync(0xffffffffu, tot, 8);
            gv[2] = __shfl_sync(0xffffffffu, tot, 16);
            gv[3] = __shfl_sync(0xffffffffu, tot, 24);

            if (lid == src) {
                int o1 = 0;
                #pragma unroll
                for (int s = 1; s < 4; s++)
                    if (gv[s] > gv[o1] || (gv[s] == gv[o1] && cand[s] < cand[o1])) o1 = s;
                int o2 = (o1 == 0) ? 1 : 0;
                #pragma unroll
                for (int s = 0; s < 4; s++) {
                    if (s == o1 || s == o2) continue;
                    if (gv[s] > gv[o2] || (gv[s] == gv[o2] && cand[s] < cand[o2])) o2 = s;
                }
                i1 = cand[o1]; i2 = cand[o2];
                v1 = row[i1];  v2 = row[i2];
            }
        }

        float S = 0.0f;
        #pragma unroll 8
        for (int e = 0; e < NEXP; e++) S += expf(row[e] - v1);
        const float p1  = expf(row[i1] - v1) / S;
        const float p2  = expf(v2 - v1) / S;
        const float inv = 1.0f / (p1 + p2 + 1e-10f);
        const size_t n = (size_t)(t0 + tid);
        w_out[2 * n]     = p1 * inv;
        w_out[2 * n + 1] = p2 * inv;
        i_out[2 * n]     = (float)i1;
        i_out[2 * n + 1] = (float)i2;
    }

    // coalesced logits store
    #pragma unroll
    for (int p = 0; p < 8; p++) {
        int id = tid + 128 * p;
        int rr = id >> 4, q = id & 15;
        float4 v;
        v.x = L[rr * LPITCH + 4 * q];
        v.y = L[rr * LPITCH + 4 * q + 1];
        v.z = L[rr * LPITCH + 4 * q + 2];
        v.w = L[rr * LPITCH + 4 * q + 3];
        *(float4*)(l_out + (size_t)(t0 + rr) * NEXP + 4 * q) = v;
    }
}

extern "C" void kernel_launch(void* const* d_in, const int* in_sizes, int n_in,
                              void* d_out, int out_size)
{
    const float* x  = (const float*)d_in[0];
    const float* Wg = (const float*)d_in[1];
    const int N = in_sizes[0] / DMODEL;       // 16384

    float* out   = (float*)d_out;
    float* w_out = out;
    float* i_out = out + (size_t)N * 2;
    float* l_out = out + (size_t)N * 4;

    wsplit_kernel<<<NEXP * DMODEL / 8 / 256, 256>>>(Wg);

    cudaFuncSetAttribute(router_mma_kernel,
                         cudaFuncAttributeMaxDynamicSharedMemorySize, SMEM_BYTES);
    router_mma_kernel<<<N / BM, NTHREADS, SMEM_BYTES>>>(x, Wg, w_out, i_out, l_out);
}